// round 8
// baseline (speedup 1.0000x reference)
#include <cuda_runtime.h>
#include <cuda_bf16.h>

// Local Moran's I:
//   xbar = mean(X)
//   xn_ij = X[ids[i][j]] - xbar
//   S_i   = sum_j w_ij * xn_ij^2
//   lag_i = sum_j w_ij * xn_ij
//   out_i = (X[i]-xbar) * lag_i * (K-1) / S_i
//
// N = 1,000,000, K = 32.
//
// Bottleneck model (validated R6/R7): L1tex wavefront throughput.
// Per row: ~30 irreducible random-gather wavefronts + 2 coalesced stream
// wavefronts. Main kernel is at that floor; this round trims the mean-stage
// overhead (fused single-kernel reduction) and main-kernel wave/tail overhead
// (persistent grid-stride warps).

#define KNBR 32
#define NUM_PARTIAL_BLOCKS 1024

__device__ float g_partials[NUM_PARTIAL_BLOCKS];
__device__ float g_mean;
__device__ unsigned int g_ticket;  // zero-initialized; wraps back to 0 each run

// ---------------- Fused mean: partial sums + last-block reduce --------------
// Deterministic: partials are indexed by blockIdx; the last arriving block
// reduces them in a fixed tree order. atomicInc wraps the ticket back to 0
// at gridDim.x-1, so graph replays see identical initial state.
__global__ __launch_bounds__(256) void moran_mean_kernel(
    const float4* __restrict__ X4, int n4, int n) {
    __shared__ float sh[256];
    float s = 0.0f;
    for (int i = blockIdx.x * blockDim.x + threadIdx.x; i < n4;
         i += gridDim.x * blockDim.x) {
        float4 v = X4[i];
        s += (v.x + v.y) + (v.z + v.w);
    }
    sh[threadIdx.x] = s;
    __syncthreads();
#pragma unroll
    for (int off = 128; off > 0; off >>= 1) {
        if (threadIdx.x < off) sh[threadIdx.x] += sh[threadIdx.x + off];
        __syncthreads();
    }

    __shared__ bool is_last;
    if (threadIdx.x == 0) {
        g_partials[blockIdx.x] = sh[0];
        __threadfence();
        unsigned int t = atomicInc(&g_ticket, NUM_PARTIAL_BLOCKS - 1);
        is_last = (t == NUM_PARTIAL_BLOCKS - 1);
    }
    __syncthreads();

    if (is_last) {
        // 256 threads, 4 partials each, fixed order -> deterministic.
        float r = 0.0f;
#pragma unroll
        for (int j = 0; j < NUM_PARTIAL_BLOCKS / 256; j++)
            r += g_partials[threadIdx.x + j * 256];
        sh[threadIdx.x] = r;
        __syncthreads();
#pragma unroll
        for (int off = 128; off > 0; off >>= 1) {
            if (threadIdx.x < off) sh[threadIdx.x] += sh[threadIdx.x + off];
            __syncthreads();
        }
        if (threadIdx.x == 0) g_mean = sh[0] / (float)n;
    }
}

// ---------------- Main Local Moran kernel (persistent) ----------------------
// 4 rows per warp-iteration, 8 lanes per row; grid-stride over warp-tiles.
__global__ __launch_bounds__(256) void moran_main_kernel(
    const float* __restrict__ X,
    const float4* __restrict__ W,    // float4 view of [N, 32]
    const int4* __restrict__ IDS,    // int4 view of [N, 32]
    float* __restrict__ out, int n) {
    const int lane = threadIdx.x & 31;
    const int row_in_warp = lane >> 3;  // 0..3
    const int seg = lane & 7;           // 0..7
    const int warp_global = (blockIdx.x * blockDim.x + threadIdx.x) >> 5;
    const int num_warps = (gridDim.x * blockDim.x) >> 5;
    const int num_tiles = (n + 3) >> 2;  // warp-tiles of 4 rows

    const float mean = g_mean;

#pragma unroll 2
    for (int tile = warp_global; tile < num_tiles; tile += num_warps) {
        int row = tile * 4 + row_in_warp;
        if (row >= n) continue;

        size_t idx4 = (size_t)row * (KNBR / 4) + seg;

        // Coalesced: warp's 32 lanes cover a contiguous 512B range each.
        int4 id = __ldcs(IDS + idx4);
        float4 w = __ldcs(W + idx4);

        // 4 random gathers per lane (irreducible wavefront cost).
        float x0 = __ldg(X + id.x) - mean;
        float x1 = __ldg(X + id.y) - mean;
        float x2 = __ldg(X + id.z) - mean;
        float x3 = __ldg(X + id.w) - mean;

        float t0 = w.x * x0;
        float t1 = w.y * x1;
        float t2 = w.z * x2;
        float t3 = w.w * x3;

        float lag = (t0 + t1) + (t2 + t3);
        float S = fmaf(t0, x0, fmaf(t1, x1, fmaf(t2, x2, t3 * x3)));

        // Reduce across the 8 lanes sharing this row.
#pragma unroll
        for (int off = 4; off > 0; off >>= 1) {
            lag += __shfl_xor_sync(0xFFFFFFFFu, lag, off);
            S += __shfl_xor_sync(0xFFFFFFFFu, S, off);
        }

        if (seg == 0) {
            float xa = __ldg(X + row) - mean;
            out[row] = xa * lag * (float)(KNBR - 1) / S;
        }
    }
}

extern "C" void kernel_launch(void* const* d_in, const int* in_sizes, int n_in,
                              void* d_out, int out_size) {
    const float* X = (const float*)d_in[0];
    const float* W = (const float*)d_in[1];
    const int* IDS = (const int*)d_in[2];
    float* out = (float*)d_out;
    int n = in_sizes[0];

    // Fused deterministic mean (one launch).
    moran_mean_kernel<<<NUM_PARTIAL_BLOCKS, 256>>>((const float4*)X, n / 4, n);

    // Persistent main kernel: 148 SMs x 8 CTAs of 256 threads.
    moran_main_kernel<<<1184, 256>>>(
        X, (const float4*)W, (const int4*)IDS, out, n);
}

// round 9
// speedup vs baseline: 1.0667x; 1.0667x over previous
#include <cuda_runtime.h>
#include <cuda_bf16.h>

// Local Moran's I:
//   xbar = mean(X)
//   xn_ij = X[ids[i][j]] - xbar
//   S_i   = sum_j w_ij * xn_ij^2
//   lag_i = sum_j w_ij * xn_ij
//   out_i = (X[i]-xbar) * lag_i * (K-1) / S_i
//
// N = 1,000,000, K = 32.
//
// Bottleneck model (validated R6-R8): L1tex wavefront throughput.
// Per row: ~30 irreducible random-gather wavefronts + ~3 coalesced
// stream/store wavefronts -> ~114us floor on 148 SMs. The R7 flat-launch
// main kernel sits at 97% of that floor; R8's persistent/unrolled variant
// regressed it (L1tex queue contention), so this round combines the R7
// main kernel with the R8 fused single-launch mean reduction.

#define KNBR 32
#define NUM_PARTIAL_BLOCKS 1024

__device__ float g_partials[NUM_PARTIAL_BLOCKS];
__device__ float g_mean;
__device__ unsigned int g_ticket;  // zero-init; atomicInc wraps to 0 per run

// ---------------- Fused mean: partial sums + last-block reduce --------------
// Deterministic: partials indexed by blockIdx; the last arriving block
// reduces them in a fixed tree order. atomicInc wraps the ticket back to 0
// at gridDim.x-1, so graph replays see identical initial state.
__global__ __launch_bounds__(256) void moran_mean_kernel(
    const float4* __restrict__ X4, int n4, int n) {
    __shared__ float sh[256];
    float s = 0.0f;
    for (int i = blockIdx.x * blockDim.x + threadIdx.x; i < n4;
         i += gridDim.x * blockDim.x) {
        float4 v = X4[i];
        s += (v.x + v.y) + (v.z + v.w);
    }
    sh[threadIdx.x] = s;
    __syncthreads();
#pragma unroll
    for (int off = 128; off > 0; off >>= 1) {
        if (threadIdx.x < off) sh[threadIdx.x] += sh[threadIdx.x + off];
        __syncthreads();
    }

    __shared__ bool is_last;
    if (threadIdx.x == 0) {
        g_partials[blockIdx.x] = sh[0];
        __threadfence();
        unsigned int t = atomicInc(&g_ticket, NUM_PARTIAL_BLOCKS - 1);
        is_last = (t == NUM_PARTIAL_BLOCKS - 1);
    }
    __syncthreads();

    if (is_last) {
        // 256 threads, 4 partials each, fixed order -> deterministic.
        float r = 0.0f;
#pragma unroll
        for (int j = 0; j < NUM_PARTIAL_BLOCKS / 256; j++)
            r += g_partials[threadIdx.x + j * 256];
        sh[threadIdx.x] = r;
        __syncthreads();
#pragma unroll
        for (int off = 128; off > 0; off >>= 1) {
            if (threadIdx.x < off) sh[threadIdx.x] += sh[threadIdx.x + off];
            __syncthreads();
        }
        if (threadIdx.x == 0) g_mean = sh[0] / (float)n;
    }
}

// ---------------- Main Local Moran kernel (flat launch, R7 structure) -------
// 4 rows per warp, 8 lanes per row. Lane l: row_local = l>>3, seg = l&7.
// Each lane handles one float4/int4 of its row; W/IDS loads are 512B
// contiguous per warp instruction (4 wavefronts for 4 rows).
__global__ __launch_bounds__(256) void moran_main_kernel(
    const float* __restrict__ X,
    const float4* __restrict__ W,    // float4 view of [N, 32]
    const int4* __restrict__ IDS,    // int4 view of [N, 32]
    float* __restrict__ out, int n) {
    int warp_global = (blockIdx.x * blockDim.x + threadIdx.x) >> 5;
    int lane = threadIdx.x & 31;
    int row = warp_global * 4 + (lane >> 3);
    int seg = lane & 7;
    if (row >= n) return;

    const float mean = g_mean;
    size_t idx4 = (size_t)row * (KNBR / 4) + seg;

    // Coalesced streams (evict-first; X must stay L2-resident).
    float4 w = __ldcs(W + idx4);
    int4 id = __ldcs(IDS + idx4);

    // 4 random gathers per lane (irreducible wavefront cost).
    float x0 = __ldg(X + id.x) - mean;
    float x1 = __ldg(X + id.y) - mean;
    float x2 = __ldg(X + id.z) - mean;
    float x3 = __ldg(X + id.w) - mean;

    float t0 = w.x * x0;
    float t1 = w.y * x1;
    float t2 = w.z * x2;
    float t3 = w.w * x3;

    float lag = (t0 + t1) + (t2 + t3);
    float S = fmaf(t0, x0, fmaf(t1, x1, fmaf(t2, x2, t3 * x3)));

    // Reduce across the 8 lanes sharing this row (offsets 4,2,1 in-group).
#pragma unroll
    for (int off = 4; off > 0; off >>= 1) {
        lag += __shfl_xor_sync(0xFFFFFFFFu, lag, off);
        S += __shfl_xor_sync(0xFFFFFFFFu, S, off);
    }

    if (seg == 0) {
        float xa = __ldg(X + row) - mean;
        out[row] = xa * lag * (float)(KNBR - 1) / S;
    }
}

extern "C" void kernel_launch(void* const* d_in, const int* in_sizes, int n_in,
                              void* d_out, int out_size) {
    const float* X = (const float*)d_in[0];
    const float* W = (const float*)d_in[1];
    const int* IDS = (const int*)d_in[2];
    float* out = (float*)d_out;
    int n = in_sizes[0];

    // Fused deterministic mean (one launch, ~4.5us).
    moran_mean_kernel<<<NUM_PARTIAL_BLOCKS, 256>>>((const float4*)X, n / 4, n);

    // Main kernel: 4 rows/warp -> 32 rows per 256-thread block.
    int threads = 256;
    int rows_per_block = (threads / 32) * 4;  // 32
    int blocks = (n + rows_per_block - 1) / rows_per_block;
    moran_main_kernel<<<blocks, threads>>>(
        X, (const float4*)W, (const int4*)IDS, out, n);
}